// round 10
// baseline (speedup 1.0000x reference)
#include <cuda_runtime.h>
#include <cstdint>
#include <math.h>

#define NT       16
#define S_LEN    4096
#define B_SZ     512
#define CHUNK    8
#define M_SPLIT  2112                      // fwd does 2112 steps, bwd 1984 (balanced)
#define NBLK     (B_SZ / 2)

typedef unsigned long long u64;

// Per-row partial results + completion counter (device globals: legal scratch).
__device__ float g_fwd[B_SZ];
__device__ float g_gold[B_SZ];
__device__ unsigned g_done = 0;

// ---- smem helpers: plain LDS/STS inside asm volatile (compiler-ordered,
// ptxas-schedulable; same-warp same-address RAW is ordered by the LSU) ----
__device__ __forceinline__ unsigned smem_addr(const void* p) {
    unsigned a;
    asm("{ .reg .u64 t; cvta.to.shared.u64 t, %1; cvt.u32.u64 %0, t; }"
        : "=r"(a) : "l"(p));
    return a;
}
__device__ __forceinline__ void sts32(unsigned addr, float v) {
    asm volatile("st.shared.f32 [%0], %1;" :: "r"(addr), "f"(v));
}
__device__ __forceinline__ void lds4(unsigned a, u64* p) {
    asm volatile("ld.shared.v2.b64 {%0,%1}, [%2];" : "=l"(p[0]), "=l"(p[1]) : "r"(a));
    asm volatile("ld.shared.v2.b64 {%0,%1}, [%2];" : "=l"(p[2]), "=l"(p[3]) : "r"(a + 16));
    asm volatile("ld.shared.v2.b64 {%0,%1}, [%2];" : "=l"(p[4]), "=l"(p[5]) : "r"(a + 32));
    asm volatile("ld.shared.v2.b64 {%0,%1}, [%2];" : "=l"(p[6]), "=l"(p[7]) : "r"(a + 48));
}

// ---- packed fp32x2 math ----
__device__ __forceinline__ u64 mul2(u64 a, u64 b) {
    u64 d; asm("mul.rn.f32x2 %0, %1, %2;" : "=l"(d) : "l"(a), "l"(b)); return d;
}
__device__ __forceinline__ u64 fma2(u64 a, u64 b, u64 c) {
    u64 d; asm("fma.rn.f32x2 %0, %1, %2, %3;" : "=l"(d) : "l"(a), "l"(b), "l"(c)); return d;
}
__device__ __forceinline__ u64 add2(u64 a, u64 b) {
    u64 d; asm("add.rn.f32x2 %0, %1, %2;" : "=l"(d) : "l"(a), "l"(b)); return d;
}
__device__ __forceinline__ u64 pack2(float lo, float hi) {
    u64 d; asm("mov.b64 %0, {%1, %2};" : "=l"(d) : "f"(lo), "f"(hi)); return d;
}
__device__ __forceinline__ void unpack2(u64 v, float& lo, float& hi) {
    asm("mov.b64 {%0, %1}, %2;" : "=f"(lo), "=f"(hi) : "l"(v));
}

// balanced packed 16-term dot: v[8] pairs vs c[8] pairs -> scalar
__device__ __forceinline__ float dot16(const u64* v, const u64* c) {
    u64 p0 = mul2(v[0], c[0]);
    u64 p1 = mul2(v[1], c[1]);
    u64 p2 = mul2(v[2], c[2]);
    u64 p3 = mul2(v[3], c[3]);
    p0 = fma2(v[4], c[4], p0);
    p1 = fma2(v[5], c[5], p1);
    p2 = fma2(v[6], c[6], p2);
    p3 = fma2(v[7], c[7], p3);
    const u64 q0 = add2(p0, p1);
    const u64 q1 = add2(p2, p3);
    const u64 qq = add2(q0, q1);
    float lo, hi;
    unpack2(qq, lo, hi);
    return lo + hi;
}

// Detect element strides (bytes) of tags/mask buffers (JAX dtype ambiguity).
__device__ __forceinline__ int detect_mask_stride(const unsigned char* mb) {
    return (mb[1] | mb[2] | mb[3]) ? 1 : 4;
}
__device__ __forceinline__ int detect_tag_stride(const void* tp) {
    const int* w = (const int*)tp;
    int nz = 0;
#pragma unroll
    for (int k = 0; k < 32; ++k) nz |= w[1 + 2 * k];   // high halves if int64
    return nz ? 4 : 8;
}

// Gold path score for one row computed by one full warp (32 lanes).
__device__ __forceinline__ void gold_row(
    int row, const unsigned char* tags_b, int tstride,
    const unsigned char* mask_b, int mstride,
    const float* emissions, const float* start_t, const float* end_t,
    const float* transitions, int lane)
{
    const unsigned char* trow = tags_b + (size_t)row * S_LEN * tstride;
    const unsigned char* mrow = mask_b + (size_t)row * S_LEN * mstride;
    const float*         erow = emissions + (size_t)row * S_LEN * NT;

    float acc = 0.0f;
    int   cnt = 0;
    for (int t = lane; t < S_LEN; t += 32) {
        const int tg = trow[(size_t)t * tstride];
        const int mm = mrow[(size_t)t * mstride];
        cnt += mm ? 1 : 0;
        if (t == 0) {
            acc += start_t[tg] + erow[tg];
        } else if (mm) {
            const int tpv = trow[(size_t)(t - 1) * tstride];
            acc += transitions[tpv * NT + tg] + erow[(size_t)t * NT + tg];
        }
    }
#pragma unroll
    for (int off = 16; off >= 1; off >>= 1) {
        acc += __shfl_xor_sync(0xffffffffu, acc, off);
        cnt += __shfl_xor_sync(0xffffffffu, cnt, off);
    }
    if (lane == 0) {
        int last = cnt - 1;
        if (last < 0) last = 0;
        const int lt = trow[(size_t)last * tstride];
        g_gold[row] = acc + end_t[lt];
    }
}

// One block = 64 threads = 2 warps, 2 batch rows.
//   warp 0: FORWARD scan t = 0..M_SPLIT-1 for both rows (16 lanes/row), then gold row0
//   warp 1: BACKWARD scan t = S-1..M_SPLIT for both rows, then gold row1
// Join: score = log( alpha_{M-1} . beta_{M-1} ) + (kA+kB) ln2.
__global__ void __launch_bounds__(64, 1) crf_fused_kernel(
    const float* __restrict__ emissions,          // [B, S, NT] f32
    const void*  __restrict__ tags_raw,           // [B, S] i32 or i64
    const void*  __restrict__ mask_raw,           // [B, S] u8 or i32 (bool)
    const float* __restrict__ transitions,        // [NT, NT] f32
    const float* __restrict__ start_t,            // [NT] f32
    const float* __restrict__ end_t,              // [NT] f32
    float* __restrict__ out)
{
    const int warp = threadIdx.x >> 5;
    const int lane = threadIdx.x & 31;
    const int j    = lane & 15;                  // tag index
    const int r    = lane >> 4;                  // row-within-warp (0/1)
    const int row  = blockIdx.x * 2 + r;

    const unsigned char* mask_b = (const unsigned char*)mask_raw;
    const unsigned char* tags_b = (const unsigned char*)tags_raw;
    const int mstride = detect_mask_stride(mask_b);
    const int tstride = detect_tag_stride(tags_raw);

    // ping-pong state buffers (one per warp) + finals for the join
    __shared__ float sbufA[2][2][NT];     // forward
    __shared__ float sbufB[2][2][NT];     // backward
    __shared__ float finA[2][NT], finB[2][NT];
    __shared__ int   kA[2], kB[2];
    __shared__ int   s_last;

    if (warp == 0) {
        // ================= FORWARD (identical inner loop to round 9) =============
        u64 eT2[8];
#pragma unroll
        for (int i = 0; i < 8; ++i)
            eT2[i] = pack2(__expf(transitions[(2 * i) * NT + j]),
                           __expf(transitions[(2 * i + 1) * NT + j]));

        const float* erow = emissions + (size_t)row * S_LEN * NT + j;
        const unsigned char* mrow = mask_b + (size_t)row * S_LEN * mstride;

        float s = __expf(start_t[j] + erow[0]);
        int   ksum = 0;

        const unsigned sb    = smem_addr(&sbufA[0][0][0]);
        const unsigned rbase = sb + (unsigned)(r * 64);
        const unsigned jb    = (unsigned)(j * 4);
        unsigned par = 0;

        sts32(rbase + jb, s);

        float ebuf[CHUNK];
        int   mbuf[CHUNK];
#pragma unroll
        for (int p = 0; p < CHUNK; ++p) {
            ebuf[p] = erow[(size_t)p * NT];
            mbuf[p] = mrow[(size_t)p * mstride];
        }

        for (int tb = 0; tb < M_SPLIT; tb += CHUNK) {
#pragma unroll
            for (int u = 0; u < CHUNK; ++u) {
                const int t = tb + u;
                const int m = (t == 0) ? 0 : mbuf[u];

                const float wpre = __expf(ebuf[u]);

                u64 v[8];
                lds4(rbase + par, v);

                const int tp = t + CHUNK;
                if (tp < M_SPLIT) {
                    ebuf[u] = erow[(size_t)tp * NT];
                    mbuf[u] = mrow[(size_t)tp * mstride];
                }

                const unsigned ub = (unsigned)v[0];
                const int kcur = (int)((ub >> 23) & 0xffu) - 127;
                const unsigned wb =
                    __float_as_uint(wpre) + 0x3f800000u - (ub & 0x7f800000u);
                const float W = __uint_as_float(wb);

                const float acc = dot16(v, eT2);

                const float ns = acc * W;
                s    = m ? ns : s;
                ksum += m * kcur;

                par ^= 128u;
                sts32(rbase + par + jb, s);
            }
        }

        finA[r][j] = s;
        if (j == 0) kA[r] = ksum;

        // gold for row (2b + 0), full warp
        gold_row(blockIdx.x * 2, tags_b, tstride, mask_b, mstride,
                 emissions, start_t, end_t, transitions, lane);
    } else {
        // ================= BACKWARD: beta_t = A^T_{t+1} beta_{t+1} ===============
        // lane j needs row j of expT: c[i] = (expT[j][2i], expT[j][2i+1])
        u64 eR2[8];
#pragma unroll
        for (int i = 0; i < 8; ++i)
            eR2[i] = pack2(__expf(transitions[j * NT + 2 * i]),
                           __expf(transitions[j * NT + 2 * i + 1]));

        const float* erow = emissions + (size_t)row * S_LEN * NT + j;
        const unsigned char* mrow = mask_b + (size_t)row * S_LEN * mstride;

        // beta_{S-1} = exp(end); store value is always  s * w_t  (w of the step
        // whose gather will consume it).
        float s = __expf(end_t[j]);
        int   ksum = 0;

        const unsigned sb    = smem_addr(&sbufB[0][0][0]);
        const unsigned rbase = sb + (unsigned)(r * 64);
        const unsigned jb    = (unsigned)(j * 4);
        unsigned par = 0;

        {   // initial store: s * w_{S-1}
            const float w0 = __expf(erow[(size_t)(S_LEN - 1) * NT]);
            sts32(rbase + jb, s * w0);
        }

        const int NB = S_LEN - M_SPLIT;           // 1984 iterations
        // iteration n: tau = S-1-n. uses mask[tau], stores with w at (tau-1).
        float ebuf[CHUNK];                        // e[tau-1]
        int   mbuf[CHUNK];                        // mask[tau]
#pragma unroll
        for (int p = 0; p < CHUNK; ++p) {
            ebuf[p] = erow[(size_t)(S_LEN - 2 - p) * NT];
            mbuf[p] = mrow[(size_t)(S_LEN - 1 - p) * mstride];
        }

        for (int nb = 0; nb < NB; nb += CHUNK) {
#pragma unroll
            for (int u = 0; u < CHUNK; ++u) {
                const int n = nb + u;
                const int m = mbuf[u];
                const float wnext = __expf(ebuf[u]);   // w_{tau-1}, off-chain

                u64 v[8];
                lds4(rbase + par, v);

                const int np = n + CHUNK;
                if (np < NB) {
                    ebuf[u] = erow[(size_t)(S_LEN - 2 - np) * NT];
                    mbuf[u] = mrow[(size_t)(S_LEN - 1 - np) * mstride];
                }

                // guarded exact 2^-k from gathered u0 (parallel to tree)
                const unsigned ub = (unsigned)v[0];
                const int ef = (int)((ub >> 23) & 0xffu);
                int   kcur;
                float f1;
                if (ef >= 1 && ef <= 253) {
                    kcur = ef - 127;
                    f1   = __uint_as_float((unsigned)(254 - ef) << 23);
                } else {
                    kcur = 0; f1 = 1.0f;
                }

                const float acc = dot16(v, eR2);       // (E u)_j

                const float ns = acc * f1;
                s    = m ? ns : s;
                ksum += m * kcur;

                par ^= 128u;
                sts32(rbase + par + jb, s * wnext);
            }
        }

        finB[r][j] = s;
        if (j == 0) kB[r] = ksum;

        // gold for row (2b + 1), full warp
        gold_row(blockIdx.x * 2 + 1, tags_b, tstride, mask_b, mstride,
                 emissions, start_t, end_t, transitions, lane);
    }

    // ================= join: score = log(alpha . beta) + (kA+kB) ln2 ============
    __syncthreads();
    if (warp == 0) {
        float prod = finA[r][j] * finB[r][j];
#pragma unroll
        for (int off = 8; off >= 1; off >>= 1)
            prod += __shfl_xor_sync(0xffffffffu, prod, off, 16);
        if (j == 0)
            g_fwd[row] = logf(prod) +
                         (float)(kA[r] + kB[r]) * 0.6931471805599453f;
    }

    // ---------------- last-block global reduction ----------------
    __syncthreads();
    if (threadIdx.x == 0) {
        __threadfence();
        const unsigned old = atomicAdd(&g_done, 1u);
        s_last = (old == NBLK - 1u) ? 1 : 0;
    }
    __syncthreads();
    if (s_last) {
        __threadfence();
        float a = 0.0f;
        for (int i = threadIdx.x; i < B_SZ; i += 64)
            a += g_fwd[i] - g_gold[i];
#pragma unroll
        for (int off = 16; off >= 1; off >>= 1)
            a += __shfl_xor_sync(0xffffffffu, a, off);
        __shared__ float wsum[2];
        if ((threadIdx.x & 31) == 0) wsum[threadIdx.x >> 5] = a;
        __syncthreads();
        if (threadIdx.x == 0) {
            out[0] = (wsum[0] + wsum[1]) * (1.0f / (float)B_SZ);
            g_done = 0;                      // reset for next graph replay
        }
    }
}

extern "C" void kernel_launch(void* const* d_in, const int* in_sizes, int n_in,
                              void* d_out, int out_size)
{
    (void)in_sizes; (void)n_in; (void)out_size;
    const float* emissions   = (const float*)d_in[0];
    const void*  tags        = d_in[1];
    const void*  mask        = d_in[2];
    const float* transitions = (const float*)d_in[3];
    const float* start_t     = (const float*)d_in[4];
    const float* end_t       = (const float*)d_in[5];

    crf_fused_kernel<<<NBLK, 64>>>(emissions, tags, mask, transitions,
                                   start_t, end_t, (float*)d_out);
}

// round 11
// speedup vs baseline: 1.0219x; 1.0219x over previous
#include <cuda_runtime.h>
#include <cstdint>
#include <math.h>

#define NT     16
#define S_LEN  4096
#define B_SZ   512
#define HALF   (S_LEN / 2)                 // 2048 steps each direction
#define CHUNK  8
#define NBLK   B_SZ                        // one block per batch row

typedef unsigned long long u64;
typedef long long s64;

// Per-row partial results + completion counter (device globals: legal scratch).
__device__ float g_fwd[B_SZ];
__device__ float g_gold[B_SZ];
__device__ unsigned g_done = 0;

// ---- smem helpers: plain LDS/STS inside asm volatile (compiler-ordered,
// ptxas-schedulable; same-warp same-address RAW is ordered by the LSU) ----
__device__ __forceinline__ unsigned smem_addr(const void* p) {
    unsigned a;
    asm("{ .reg .u64 t; cvta.to.shared.u64 t, %1; cvt.u32.u64 %0, t; }"
        : "=r"(a) : "l"(p));
    return a;
}
__device__ __forceinline__ void sts32(unsigned addr, float v) {
    asm volatile("st.shared.f32 [%0], %1;" :: "r"(addr), "f"(v));
}
__device__ __forceinline__ void lds4(unsigned a, u64* p) {
    asm volatile("ld.shared.v2.b64 {%0,%1}, [%2];" : "=l"(p[0]), "=l"(p[1]) : "r"(a));
    asm volatile("ld.shared.v2.b64 {%0,%1}, [%2];" : "=l"(p[2]), "=l"(p[3]) : "r"(a + 16));
    asm volatile("ld.shared.v2.b64 {%0,%1}, [%2];" : "=l"(p[4]), "=l"(p[5]) : "r"(a + 32));
    asm volatile("ld.shared.v2.b64 {%0,%1}, [%2];" : "=l"(p[6]), "=l"(p[7]) : "r"(a + 48));
}

// ---- packed fp32x2 math ----
__device__ __forceinline__ u64 mul2(u64 a, u64 b) {
    u64 d; asm("mul.rn.f32x2 %0, %1, %2;" : "=l"(d) : "l"(a), "l"(b)); return d;
}
__device__ __forceinline__ u64 fma2(u64 a, u64 b, u64 c) {
    u64 d; asm("fma.rn.f32x2 %0, %1, %2, %3;" : "=l"(d) : "l"(a), "l"(b), "l"(c)); return d;
}
__device__ __forceinline__ u64 add2(u64 a, u64 b) {
    u64 d; asm("add.rn.f32x2 %0, %1, %2;" : "=l"(d) : "l"(a), "l"(b)); return d;
}
__device__ __forceinline__ u64 pack2(float lo, float hi) {
    u64 d; asm("mov.b64 %0, {%1, %2};" : "=l"(d) : "f"(lo), "f"(hi)); return d;
}
__device__ __forceinline__ void unpack2(u64 v, float& lo, float& hi) {
    asm("mov.b64 {%0, %1}, %2;" : "=f"(lo), "=f"(hi) : "l"(v));
}

// balanced packed 16-term dot: v[8] pairs vs c[8] pairs -> scalar
__device__ __forceinline__ float dot16(const u64* v, const u64* c) {
    u64 p0 = mul2(v[0], c[0]);
    u64 p1 = mul2(v[1], c[1]);
    u64 p2 = mul2(v[2], c[2]);
    u64 p3 = mul2(v[3], c[3]);
    p0 = fma2(v[4], c[4], p0);
    p1 = fma2(v[5], c[5], p1);
    p2 = fma2(v[6], c[6], p2);
    p3 = fma2(v[7], c[7], p3);
    const u64 q0 = add2(p0, p1);
    const u64 q1 = add2(p2, p3);
    const u64 qq = add2(q0, q1);
    float lo, hi;
    unpack2(qq, lo, hi);
    return lo + hi;
}

// Detect element strides (bytes) of tags/mask buffers (JAX dtype ambiguity).
__device__ __forceinline__ int detect_mask_stride(const unsigned char* mb) {
    return (mb[1] | mb[2] | mb[3]) ? 1 : 4;
}
__device__ __forceinline__ int detect_tag_stride(const void* tp) {
    const int* w = (const int*)tp;
    int nz = 0;
#pragma unroll
    for (int k = 0; k < 32; ++k) nz |= w[1 + 2 * k];   // high halves if int64
    return nz ? 4 : 8;
}

// Gold path score for one row, one full warp (32 lanes). Runs concurrently
// with the scan warp (round-9-proven placement).
__device__ __forceinline__ void gold_row(
    int row, const unsigned char* tags_b, int tstride,
    const unsigned char* mask_b, int mstride,
    const float* emissions, const float* start_t, const float* end_t,
    const float* transitions, int lane)
{
    const unsigned char* trow = tags_b + (size_t)row * S_LEN * tstride;
    const unsigned char* mrow = mask_b + (size_t)row * S_LEN * mstride;
    const float*         erow = emissions + (size_t)row * S_LEN * NT;

    float acc = 0.0f;
    int   cnt = 0;
    for (int t = lane; t < S_LEN; t += 32) {
        const int tg = trow[(size_t)t * tstride];
        const int mm = mrow[(size_t)t * mstride];
        cnt += mm ? 1 : 0;
        if (t == 0) {
            acc += start_t[tg] + erow[tg];
        } else if (mm) {
            const int tpv = trow[(size_t)(t - 1) * tstride];
            acc += transitions[tpv * NT + tg] + erow[(size_t)t * NT + tg];
        }
    }
#pragma unroll
    for (int off = 16; off >= 1; off >>= 1) {
        acc += __shfl_xor_sync(0xffffffffu, acc, off);
        cnt += __shfl_xor_sync(0xffffffffu, cnt, off);
    }
    if (lane == 0) {
        int last = cnt - 1;
        if (last < 0) last = 0;
        const int lt = trow[(size_t)last * tstride];
        g_gold[row] = acc + end_t[lt];
    }
}

// One block = 64 threads = 2 warps, 1 batch row.
//   warp 0: scan — lanes 0-15 forward t=0..2047, lanes 16-31 backward t=4095..2048
//           (single unified instruction stream; only per-lane operands differ)
//   warp 1: gold path score (concurrent, shares L2 locality with the scan)
// Join: score = log( alpha_{2047} . beta ) + (kF+kB) ln2.
__global__ void __launch_bounds__(64, 1) crf_fused_kernel(
    const float* __restrict__ emissions,          // [B, S, NT] f32
    const void*  __restrict__ tags_raw,           // [B, S] i32 or i64
    const void*  __restrict__ mask_raw,           // [B, S] u8 or i32 (bool)
    const float* __restrict__ transitions,        // [NT, NT] f32
    const float* __restrict__ start_t,            // [NT] f32
    const float* __restrict__ end_t,              // [NT] f32
    float* __restrict__ out)
{
    const int warp = threadIdx.x >> 5;
    const int lane = threadIdx.x & 31;
    const int j    = lane & 15;                  // tag index
    const int dir  = lane >> 4;                  // 0 = forward, 1 = backward
    const int row  = blockIdx.x;

    const unsigned char* mask_b = (const unsigned char*)mask_raw;
    const unsigned char* tags_b = (const unsigned char*)tags_raw;
    const int mstride = detect_mask_stride(mask_b);
    const int tstride = detect_tag_stride(tags_raw);

    // ping-pong state: [parity][dir][tag]  (scan-warp private)
    __shared__ float sbuf[2][2][NT];
    __shared__ int   s_last;

    if (warp == 0) {
        // ---------------- unified bidirectional scan ----------------
        // dot constants: fwd lane j = column j of expT; bwd lane j = row j.
        u64 C2[8];
#pragma unroll
        for (int i = 0; i < 8; ++i) {
            const int ia = dir ? (j * NT + 2 * i)     : ((2 * i) * NT + j);
            const int ib = dir ? (j * NT + 2 * i + 1) : ((2 * i + 1) * NT + j);
            C2[i] = pack2(__expf(transitions[ia]), __expf(transitions[ib]));
        }

        const float* erow = emissions + (size_t)row * S_LEN * NT + j;
        const unsigned char* mrowb = mask_b + (size_t)row * S_LEN * mstride;

        // per-lane walk: fwd ascending from t=0; bwd emissions descending from
        // t=S-2 (w consumed by store), mask descending from t=S-1.
        const float* ep = erow + (dir ? (size_t)(S_LEN - 2) * NT : 0);
        const s64 estep  = dir ? -(s64)NT : (s64)NT;
        const unsigned char* mp = mrowb + (dir ? (size_t)(S_LEN - 1) * mstride : 0);
        const s64 mbstep = dir ? -(s64)mstride : (s64)mstride;

        // init state + initial publish (parity 0)
        float s, sv0;
        if (dir == 0) {
            s   = __expf(start_t[j] + erow[0]);
            sv0 = s;
        } else {
            s   = __expf(end_t[j]);
            sv0 = s * __expf(erow[(size_t)(S_LEN - 1) * NT]);   // fold w_{S-1}
        }
        int ksum = 0;

        const unsigned sb   = smem_addr(&sbuf[0][0][0]);
        const unsigned base = sb + (unsigned)(dir * 64);
        const unsigned jb   = (unsigned)(j * 4);
        unsigned par = 0;

        sts32(base + jb, sv0);

        // register prefetch pipeline (per-lane pointers)
        float ebuf[CHUNK];
        int   mbuf[CHUNK];
#pragma unroll
        for (int p = 0; p < CHUNK; ++p) {
            ebuf[p] = ep[(s64)p * estep];
            mbuf[p] = mp[(s64)p * mbstep];
        }
        if (dir == 0) mbuf[0] = 0;                 // fwd step 0 is the init

        for (int tb = 0; tb < HALF; tb += CHUNK) {
#pragma unroll
            for (int u = 0; u < CHUNK; ++u) {
                const int m = mbuf[u];
                const float w = __expf(ebuf[u]);   // off-chain (loaded CHUNK ago)

                // gather own direction's state (4x LDS.128, 2 bcast groups)
                u64 v[8];
                lds4(base + par, v);

                // prefetch t+CHUNK
                const int np = tb + u + CHUNK;
                if (np < HALF) {
                    ebuf[u] = ep[(s64)np * estep];
                    mbuf[u] = mp[(s64)np * mbstep];
                }

                // per-lane off-chain operands:
                //   fwd: P = w * 2^-k (emission+rescale fold), Q = 1
                //   bwd: P = 2^-k,                             Q = w
                const unsigned pb =
                    dir ? 0x7F000000u : (__float_as_uint(w) + 0x3f800000u);
                const float Q = dir ? w : 1.0f;

                // on-chain: exponent extract + fold (LOP3+IADD3, ready at LDS+8)
                const unsigned ub = (unsigned)v[0];
                const int kcur = (int)((ub >> 23) & 0xffu) - 127;
                const float P  = __uint_as_float(pb - (ub & 0x7f800000u));

                const float acc = dot16(v, C2);

                const float ns = acc * P;
                s    = m ? ns : s;
                ksum += m * kcur;

                // publish to other parity (store-side emission fold for bwd)
                par ^= 128u;
                sts32(base + par + jb, s * Q);
            }
        }

        // join: alpha_{2047}(j) * beta(j), sum over j, add scale counts
        const float spart = __shfl_xor_sync(0xffffffffu, s, 16);
        const int   kpart = __shfl_xor_sync(0xffffffffu, ksum, 16);
        float prod = s * spart;
#pragma unroll
        for (int off = 8; off >= 1; off >>= 1)
            prod += __shfl_xor_sync(0xffffffffu, prod, off, 16);
        if (lane == 0)
            g_fwd[row] = logf(prod) +
                         (float)(ksum + kpart) * 0.6931471805599453f;
    } else {
        // ---------------- gold path score (concurrent) ----------------
        gold_row(row, tags_b, tstride, mask_b, mstride,
                 emissions, start_t, end_t, transitions, lane);
    }

    // ---------------- last-block global reduction ----------------
    __syncthreads();
    if (threadIdx.x == 0) {
        __threadfence();
        const unsigned old = atomicAdd(&g_done, 1u);
        s_last = (old == NBLK - 1u) ? 1 : 0;
    }
    __syncthreads();
    if (s_last) {
        __threadfence();
        float a = 0.0f;
        for (int i = threadIdx.x; i < B_SZ; i += 64)
            a += g_fwd[i] - g_gold[i];
#pragma unroll
        for (int off = 16; off >= 1; off >>= 1)
            a += __shfl_xor_sync(0xffffffffu, a, off);
        __shared__ float wsum[2];
        if ((threadIdx.x & 31) == 0) wsum[threadIdx.x >> 5] = a;
        __syncthreads();
        if (threadIdx.x == 0) {
            out[0] = (wsum[0] + wsum[1]) * (1.0f / (float)B_SZ);
            g_done = 0;                      // reset for next graph replay
        }
    }
}

extern "C" void kernel_launch(void* const* d_in, const int* in_sizes, int n_in,
                              void* d_out, int out_size)
{
    (void)in_sizes; (void)n_in; (void)out_size;
    const float* emissions   = (const float*)d_in[0];
    const void*  tags        = d_in[1];
    const void*  mask        = d_in[2];
    const float* transitions = (const float*)d_in[3];
    const float* start_t     = (const float*)d_in[4];
    const float* end_t       = (const float*)d_in[5];

    crf_fused_kernel<<<NBLK, 64>>>(emissions, tags, mask, transitions,
                                   start_t, end_t, (float*)d_out);
}

// round 13
// speedup vs baseline: 1.0284x; 1.0064x over previous
#include <cuda_runtime.h>
#include <cstdint>
#include <math.h>

#define NT     16
#define S_LEN  4096
#define B_SZ   512
#define HALF   (S_LEN / 2)                 // 2048 unified iterations
#define CHUNK  8
#define NBLK   B_SZ                        // one block per batch row

typedef unsigned long long u64;

// Per-row partial results + completion counter (device globals: legal scratch).
__device__ float g_fwd[B_SZ];
__device__ float g_gold[B_SZ];
__device__ unsigned g_done = 0;

// ---- smem helpers: plain LDS/STS inside asm volatile (compiler-ordered,
// ptxas-schedulable; same-warp same-address RAW is ordered by the LSU) ----
__device__ __forceinline__ unsigned smem_addr(const void* p) {
    unsigned a;
    asm("{ .reg .u64 t; cvta.to.shared.u64 t, %1; cvt.u32.u64 %0, t; }"
        : "=r"(a) : "l"(p));
    return a;
}
__device__ __forceinline__ void sts32(unsigned addr, float v) {
    asm volatile("st.shared.f32 [%0], %1;" :: "r"(addr), "f"(v));
}
__device__ __forceinline__ void lds4(unsigned a, u64* p) {
    asm volatile("ld.shared.v2.b64 {%0,%1}, [%2];" : "=l"(p[0]), "=l"(p[1]) : "r"(a));
    asm volatile("ld.shared.v2.b64 {%0,%1}, [%2];" : "=l"(p[2]), "=l"(p[3]) : "r"(a + 16));
    asm volatile("ld.shared.v2.b64 {%0,%1}, [%2];" : "=l"(p[4]), "=l"(p[5]) : "r"(a + 32));
    asm volatile("ld.shared.v2.b64 {%0,%1}, [%2];" : "=l"(p[6]), "=l"(p[7]) : "r"(a + 48));
}

// ---- packed fp32x2 math ----
__device__ __forceinline__ u64 mul2(u64 a, u64 b) {
    u64 d; asm("mul.rn.f32x2 %0, %1, %2;" : "=l"(d) : "l"(a), "l"(b)); return d;
}
__device__ __forceinline__ u64 fma2(u64 a, u64 b, u64 c) {
    u64 d; asm("fma.rn.f32x2 %0, %1, %2, %3;" : "=l"(d) : "l"(a), "l"(b), "l"(c)); return d;
}
__device__ __forceinline__ u64 add2(u64 a, u64 b) {
    u64 d; asm("add.rn.f32x2 %0, %1, %2;" : "=l"(d) : "l"(a), "l"(b)); return d;
}
__device__ __forceinline__ u64 pack2(float lo, float hi) {
    u64 d; asm("mov.b64 %0, {%1, %2};" : "=l"(d) : "f"(lo), "f"(hi)); return d;
}
__device__ __forceinline__ void unpack2(u64 v, float& lo, float& hi) {
    asm("mov.b64 {%0, %1}, %2;" : "=f"(lo), "=f"(hi) : "l"(v));
}

// balanced packed 16-term dot: v[8] pairs vs c[8] pairs -> scalar
__device__ __forceinline__ float dot16(const u64* v, const u64* c) {
    u64 p0 = mul2(v[0], c[0]);
    u64 p1 = mul2(v[1], c[1]);
    u64 p2 = mul2(v[2], c[2]);
    u64 p3 = mul2(v[3], c[3]);
    p0 = fma2(v[4], c[4], p0);
    p1 = fma2(v[5], c[5], p1);
    p2 = fma2(v[6], c[6], p2);
    p3 = fma2(v[7], c[7], p3);
    const u64 q0 = add2(p0, p1);
    const u64 q1 = add2(p2, p3);
    const u64 qq = add2(q0, q1);
    float lo, hi;
    unpack2(qq, lo, hi);
    return lo + hi;
}

// Detect element strides (bytes) of tags/mask buffers (JAX dtype ambiguity).
__device__ __forceinline__ int detect_mask_stride(const unsigned char* mb) {
    return (mb[1] | mb[2] | mb[3]) ? 1 : 4;
}
__device__ __forceinline__ int detect_tag_stride(const void* tp) {
    const int* w = (const int*)tp;
    int nz = 0;
#pragma unroll
    for (int k = 0; k < 32; ++k) nz |= w[1 + 2 * k];   // high halves if int64
    return nz ? 4 : 8;
}

// Gold path score for one row, one full warp (32 lanes).
__device__ __forceinline__ void gold_row(
    int row, const unsigned char* tags_b, int tstride,
    const unsigned char* mask_b, int mstride,
    const float* emissions, const float* start_t, const float* end_t,
    const float* transitions, int lane)
{
    const unsigned char* trow = tags_b + (size_t)row * S_LEN * tstride;
    const unsigned char* mrow = mask_b + (size_t)row * S_LEN * mstride;
    const float*         erow = emissions + (size_t)row * S_LEN * NT;

    float acc = 0.0f;
    int   cnt = 0;
    for (int t = lane; t < S_LEN; t += 32) {
        const int tg = trow[(size_t)t * tstride];
        const int mm = mrow[(size_t)t * mstride];
        cnt += mm ? 1 : 0;
        if (t == 0) {
            acc += start_t[tg] + erow[tg];
        } else if (mm) {
            const int tpv = trow[(size_t)(t - 1) * tstride];
            acc += transitions[tpv * NT + tg] + erow[(size_t)t * NT + tg];
        }
    }
#pragma unroll
    for (int off = 16; off >= 1; off >>= 1) {
        acc += __shfl_xor_sync(0xffffffffu, acc, off);
        cnt += __shfl_xor_sync(0xffffffffu, cnt, off);
    }
    if (lane == 0) {
        int last = cnt - 1;
        if (last < 0) last = 0;
        const int lt = trow[(size_t)last * tstride];
        g_gold[row] = acc + end_t[lt];
    }
}

// One block = 64 threads = 2 warps, 1 batch row.
//   warp 0 scan: lanes 0-15 forward  alpha_t = w_t . (E^T alpha_{t-1}),  t=0..2047
//                lanes 16-31 delta   delta_t = w_t . (E   delta_{t+1}),  t=4095..2048
//     -> the SAME branchless round-9 body for both halves (only operands differ).
//   warp 1: gold path score (concurrent).
// Join: logZ = sum_j (E^T alpha_2047)_j * delta_2048_j  (+ scale counts).
__global__ void __launch_bounds__(64, 1) crf_fused_kernel(
    const float* __restrict__ emissions,          // [B, S, NT] f32
    const void*  __restrict__ tags_raw,           // [B, S] i32 or i64
    const void*  __restrict__ mask_raw,           // [B, S] u8 or i32 (bool)
    const float* __restrict__ transitions,        // [NT, NT] f32
    const float* __restrict__ start_t,            // [NT] f32
    const float* __restrict__ end_t,              // [NT] f32
    float* __restrict__ out)
{
    const int warp = threadIdx.x >> 5;
    const int lane = threadIdx.x & 31;
    const int j    = lane & 15;                  // tag index
    const int dir  = lane >> 4;                  // 0 = forward, 1 = backward
    const int row  = blockIdx.x;

    const unsigned char* mask_b = (const unsigned char*)mask_raw;
    const unsigned char* tags_b = (const unsigned char*)tags_raw;
    const int mstride = detect_mask_stride(mask_b);
    const int tstride = detect_tag_stride(tags_raw);

    // ping-pong state: [parity][dir][tag]  (scan-warp private)
    __shared__ float sbuf[2][2][NT];
    __shared__ int   s_last;

    if (warp == 0) {
        // ---------------- unified bidirectional scan (delta transform) ----------
        // fwd lane j: column j of expT.  bwd lane j: row j of expT.
        u64 C2[8];
#pragma unroll
        for (int i = 0; i < 8; ++i) {
            const int ia = dir ? (j * NT + 2 * i)     : ((2 * i) * NT + j);
            const int ib = dir ? (j * NT + 2 * i + 1) : ((2 * i + 1) * NT + j);
            C2[i] = pack2(__expf(transitions[ia]), __expf(transitions[ib]));
        }

        const float* erow = emissions + (size_t)row * S_LEN * NT + j;
        const unsigned char* mrowb = mask_b + (size_t)row * S_LEN * mstride;
        const float dirf = dir ? 1.0f : 0.0f;

        // prologue prefetch (iteration i: fwd t=i; bwd t=S-1-i, mask at t+1)
        float ebuf[CHUNK];
        int   mbuf[CHUNK];
#pragma unroll
        for (int p = 0; p < CHUNK; ++p) {
            const int et = dir ? (S_LEN - 1 - p) : p;
            const int mt = dir ? ((p == 0) ? S_LEN - 1 : S_LEN - p) : p;
            ebuf[p] = erow[(size_t)et * NT];
            mbuf[p] = mrowb[(size_t)mt * mstride];
        }
        mbuf[0] = 0;                              // iteration 0 is the init step

        // steady-state prefetch pointers (pure pointer-bump, no IMAD.WIDE)
        const int estep = dir ? -NT : NT;         // elements
        const int mstep = dir ? -mstride : mstride;
        const float* epf = erow + (dir ? (size_t)(S_LEN - 1 - CHUNK) * NT
                                       : (size_t)CHUNK * NT);
        const unsigned char* mpf = mrowb + (dir ? (size_t)(S_LEN - CHUNK) * mstride
                                                : (size_t)CHUNK * mstride);

        // init: fwd alpha_0 = exp(start + e_0); bwd delta_{S-1} = exp(end + e_{S-1})
        float s = __expf((dir ? end_t[j] : start_t[j]) + ebuf[0]);
        float eprev = ebuf[0];
        int   ksum = 0;

        const unsigned sb   = smem_addr(&sbuf[0][0][0]);
        const unsigned base = sb + (unsigned)(dir * 64);
        const unsigned jb   = (unsigned)(j * 4);
        unsigned par = 0;

        sts32(base + jb, s);                      // publish init (parity 0)

        for (int tb = 0; tb < HALF; tb += CHUNK) {
#pragma unroll
            for (int u = 0; u < CHUNK; ++u) {
                const float e = ebuf[u];
                const int   m = mbuf[u];

                // masked-step arm: fwd keep s; bwd s * exp(e_t - e_{t+1}).
                // unified: R = exp((e - eprev) * dirf); exp(0)=1 for fwd.
                const float R  = __expf((e - eprev) * dirf);
                const float sR = s * R;
                const float w  = __expf(e);
                const unsigned pb = __float_as_uint(w) + 0x3f800000u;

                // gather own-direction state (4x LDS.128 broadcast)
                u64 v[8];
                lds4(base + par, v);

                // prefetch (always in-bounds: indices stay inside the row)
                ebuf[u] = *epf;  epf += estep;
                mbuf[u] = *mpf;  mpf += mstep;

                // on-chain fold: P = w * 2^-k from gathered state[0]'s exponent
                const unsigned ub = (unsigned)v[0];
                const int kcur = (int)((ub >> 23) & 0xffu) - 127;
                const float P  = __uint_as_float(pb - (ub & 0x7f800000u));

                const float acc = dot16(v, C2);

                const float ns = acc * P;
                s    = m ? ns : sR;
                ksum += m * kcur;
                eprev = e;

                par ^= 128u;
                sts32(base + par + jb, s);
            }
        }

        // ---------------- join (ALL 32 lanes participate in every shfl) --------
        u64 vf[8];
        lds4(base + par, vf);
        const float y = dot16(vf, C2);     // fwd lanes: (E^T alpha_2047)_j

        // cross-half exchange: fwd lanes read bwd partner (lane+16);
        // bwd lanes read fwd partner (wraps mod 32) — defined, value unused.
        const float d  = __shfl_sync(0xffffffffu, s,    (lane + 16) & 31);
        const int   kB = __shfl_sync(0xffffffffu, ksum, (lane + 16) & 31);

        const int m2048 = mrowb[(size_t)(HALF - (int)dir * HALF) * mstride +
                                (size_t)dir * 0 + (dir ? 0 : 0)] , mju =
                          mask_b[(size_t)row * S_LEN * mstride +
                                 (size_t)HALF * mstride];
        (void)m2048;
        // m=1: logZ = sum y_j * delta_j ; m=0: beta_2047 = beta_2048
        //   -> sum alpha_j * delta_j / w_{2048,j}
        const float em = emissions[((size_t)row * S_LEN + HALF) * NT + j];
        const float term = mju ? (y * d) : (s * d * __expf(-em));

        float z = term;
#pragma unroll
        for (int off = 8; off >= 1; off >>= 1)
            z += __shfl_xor_sync(0xffffffffu, z, off, 16);
        if (lane == 0)
            g_fwd[row] = logf(z) + (float)(ksum + kB) * 0.6931471805599453f;
    } else {
        // ---------------- gold path score (concurrent) ----------------
        gold_row(row, tags_b, tstride, mask_b, mstride,
                 emissions, start_t, end_t, transitions, lane);
    }

    // ---------------- last-block global reduction ----------------
    __syncthreads();
    if (threadIdx.x == 0) {
        __threadfence();
        const unsigned old = atomicAdd(&g_done, 1u);
        s_last = (old == NBLK - 1u) ? 1 : 0;
    }
    __syncthreads();
    if (s_last) {
        __threadfence();
        float a = 0.0f;
        for (int i = threadIdx.x; i < B_SZ; i += 64)
            a += g_fwd[i] - g_gold[i];
#pragma unroll
        for (int off = 16; off >= 1; off >>= 1)
            a += __shfl_xor_sync(0xffffffffu, a, off);
        __shared__ float wsum[2];
        if ((threadIdx.x & 31) == 0) wsum[threadIdx.x >> 5] = a;
        __syncthreads();
        if (threadIdx.x == 0) {
            out[0] = (wsum[0] + wsum[1]) * (1.0f / (float)B_SZ);
            g_done = 0;                      // reset for next graph replay
        }
    }
}

extern "C" void kernel_launch(void* const* d_in, const int* in_sizes, int n_in,
                              void* d_out, int out_size)
{
    (void)in_sizes; (void)n_in; (void)out_size;
    const float* emissions   = (const float*)d_in[0];
    const void*  tags        = d_in[1];
    const void*  mask        = d_in[2];
    const float* transitions = (const float*)d_in[3];
    const float* start_t     = (const float*)d_in[4];
    const float* end_t       = (const float*)d_in[5];

    crf_fused_kernel<<<NBLK, 64>>>(emissions, tags, mask, transitions,
                                   start_t, end_t, (float*)d_out);
}

// round 14
// speedup vs baseline: 1.3369x; 1.3000x over previous
#include <cuda_runtime.h>
#include <cstdint>
#include <math.h>

#define NT     16
#define S_LEN  4096
#define B_SZ   512
#define HALF   (S_LEN / 2)                 // 2048 iterations
#define CHUNK  8
#define NBLK   (B_SZ / 2)                  // 256 blocks, 2 rows each

typedef unsigned long long u64;

// Per-row partial results + completion counter (device globals: legal scratch).
__device__ float g_fwd[B_SZ];
__device__ float g_gold[B_SZ];
__device__ unsigned g_done = 0;

// ---- smem helpers ----
__device__ __forceinline__ unsigned smem_addr(const void* p) {
    unsigned a;
    asm("{ .reg .u64 t; cvta.to.shared.u64 t, %1; cvt.u32.u64 %0, t; }"
        : "=r"(a) : "l"(p));
    return a;
}
__device__ __forceinline__ void sts64(unsigned addr, float a, float b) {
    asm volatile("st.shared.v2.f32 [%0], {%1, %2};" :: "r"(addr), "f"(a), "f"(b));
}
__device__ __forceinline__ void lds4(unsigned a, u64* p) {
    asm volatile("ld.shared.v2.b64 {%0,%1}, [%2];" : "=l"(p[0]), "=l"(p[1]) : "r"(a));
    asm volatile("ld.shared.v2.b64 {%0,%1}, [%2];" : "=l"(p[2]), "=l"(p[3]) : "r"(a + 16));
    asm volatile("ld.shared.v2.b64 {%0,%1}, [%2];" : "=l"(p[4]), "=l"(p[5]) : "r"(a + 32));
    asm volatile("ld.shared.v2.b64 {%0,%1}, [%2];" : "=l"(p[6]), "=l"(p[7]) : "r"(a + 48));
}

// ---- packed fp32x2 math ----
__device__ __forceinline__ u64 mul2(u64 a, u64 b) {
    u64 d; asm("mul.rn.f32x2 %0, %1, %2;" : "=l"(d) : "l"(a), "l"(b)); return d;
}
__device__ __forceinline__ u64 fma2(u64 a, u64 b, u64 c) {
    u64 d; asm("fma.rn.f32x2 %0, %1, %2, %3;" : "=l"(d) : "l"(a), "l"(b), "l"(c)); return d;
}
__device__ __forceinline__ u64 add2(u64 a, u64 b) {
    u64 d; asm("add.rn.f32x2 %0, %1, %2;" : "=l"(d) : "l"(a), "l"(b)); return d;
}
__device__ __forceinline__ u64 pack2(float lo, float hi) {
    u64 d; asm("mov.b64 %0, {%1, %2};" : "=l"(d) : "f"(lo), "f"(hi)); return d;
}
__device__ __forceinline__ void unpack2(u64 v, float& lo, float& hi) {
    asm("mov.b64 {%0, %1}, %2;" : "=f"(lo), "=f"(hi) : "l"(v));
}

__device__ __forceinline__ float dot16(const u64* v, const u64* c) {
    u64 p0 = mul2(v[0], c[0]);
    u64 p1 = mul2(v[1], c[1]);
    u64 p2 = mul2(v[2], c[2]);
    u64 p3 = mul2(v[3], c[3]);
    p0 = fma2(v[4], c[4], p0);
    p1 = fma2(v[5], c[5], p1);
    p2 = fma2(v[6], c[6], p2);
    p3 = fma2(v[7], c[7], p3);
    const u64 q0 = add2(p0, p1);
    const u64 q1 = add2(p2, p3);
    const u64 qq = add2(q0, q1);
    float lo, hi;
    unpack2(qq, lo, hi);
    return lo + hi;
}

// Detect element strides (bytes) of tags/mask buffers (JAX dtype ambiguity).
__device__ __forceinline__ int detect_mask_stride(const unsigned char* mb) {
    return (mb[1] | mb[2] | mb[3]) ? 1 : 4;
}
__device__ __forceinline__ int detect_tag_stride(const void* tp) {
    const int* w = (const int*)tp;
    int nz = 0;
#pragma unroll
    for (int k = 0; k < 32; ++k) nz |= w[1 + 2 * k];
    return nz ? 4 : 8;
}

// One block = 64 threads = 2 warps, 2 batch rows.
//   warp 0: bidirectional scan, 4 streams of 8 lanes:
//           q = lane>>3: dir = q>>1, r = q&1; lane owns components (2h, 2h+1).
//           fwd: alpha_t = w_t.(E^T alpha_{t-1});  bwd (delta): d_t = (E d_{t+1}).w_t
//   warp 1: gold path score for both rows (verbatim round-9 code).
__global__ void __launch_bounds__(64, 1) crf_fused_kernel(
    const float* __restrict__ emissions,          // [B, S, NT] f32
    const void*  __restrict__ tags_raw,           // [B, S] i32 or i64
    const void*  __restrict__ mask_raw,           // [B, S] u8 or i32 (bool)
    const float* __restrict__ transitions,        // [NT, NT] f32
    const float* __restrict__ start_t,            // [NT] f32
    const float* __restrict__ end_t,              // [NT] f32
    float* __restrict__ out)
{
    const int warp = threadIdx.x >> 5;
    const int lane = threadIdx.x & 31;

    const unsigned char* mask_b = (const unsigned char*)mask_raw;
    const unsigned char* tags_b = (const unsigned char*)tags_raw;
    const int mstride = detect_mask_stride(mask_b);
    const int tstride = detect_tag_stride(tags_raw);

    // ping-pong state: [parity][stream(4)][tag(16)] floats  (warp-0 private)
    __shared__ float sbuf[2][4][NT];
    __shared__ int   s_last;

    if (warp == 0) {
        const int q   = lane >> 3;                // stream id
        const int dir = q >> 1;                   // 0 fwd, 1 bwd
        const int r   = q & 1;                    // row within block
        const int h   = lane & 7;                 // owns tags 2h, 2h+1
        const int j0  = 2 * h, j1 = 2 * h + 1;
        const int row = blockIdx.x * 2 + r;

        // dot constants: fwd = columns j0/j1 of expT; bwd = rows j0/j1.
        u64 Ca[8], Cb[8];
#pragma unroll
        for (int i = 0; i < 8; ++i) {
            const int a0 = dir ? (j0 * NT + 2 * i)     : ((2 * i) * NT + j0);
            const int a1 = dir ? (j0 * NT + 2 * i + 1) : ((2 * i + 1) * NT + j0);
            const int b0 = dir ? (j1 * NT + 2 * i)     : ((2 * i) * NT + j1);
            const int b1 = dir ? (j1 * NT + 2 * i + 1) : ((2 * i + 1) * NT + j1);
            Ca[i] = pack2(__expf(transitions[a0]), __expf(transitions[a1]));
            Cb[i] = pack2(__expf(transitions[b0]), __expf(transitions[b1]));
        }

        const float2* erow2 =
            reinterpret_cast<const float2*>(emissions + (size_t)row * S_LEN * NT) + h;
        const unsigned char* mrowb = mask_b + (size_t)row * S_LEN * mstride;
        const float dirf = dir ? 1.0f : 0.0f;

        // prologue prefetch. iteration i: fwd e_i, m_i; bwd e_{S-1-i}, m_{S-i}.
        float2 ebuf[CHUNK];
        int    mbuf[CHUNK];
#pragma unroll
        for (int p = 0; p < CHUNK; ++p) {
            const int et = dir ? (S_LEN - 1 - p) : p;
            const int mt = dir ? ((p == 0) ? S_LEN - 1 : S_LEN - p) : p;
            ebuf[p] = erow2[(size_t)et * 8];
            mbuf[p] = mrowb[(size_t)mt * mstride];
        }
        mbuf[0] = 0;                              // iteration 0 = init step

        // steady-state prefetch pointers (pointer-bump only; always in-bounds)
        const int estep = dir ? -8 : 8;           // float2 units per t
        const int mstep = dir ? -mstride : mstride;
        const float2* epf = erow2 + (dir ? (size_t)(S_LEN - 1 - CHUNK) * 8
                                         : (size_t)CHUNK * 8);
        const unsigned char* mpf = mrowb + (dir ? (size_t)(S_LEN - CHUNK) * mstride
                                                : (size_t)CHUNK * mstride);

        // init: fwd alpha_0 = exp(start + e_0); bwd d_{S-1} = exp(end + e_{S-1})
        const float base0 = dir ? end_t[j0] : start_t[j0];
        const float base1 = dir ? end_t[j1] : start_t[j1];
        float s0 = __expf(base0 + ebuf[0].x);
        float s1 = __expf(base1 + ebuf[0].y);
        float2 ep = ebuf[0];
        int    ksum = 0;

        const unsigned sb   = smem_addr(&sbuf[0][0][0]);
        const unsigned base = sb + (unsigned)(q * 64);
        const unsigned hb   = (unsigned)(h * 8);
        unsigned par = 0;                          // parity byte offset (0 / 256)

        sts64(base + hb, s0, s1);                  // publish init (parity 0)

        for (int tb = 0; tb < HALF; tb += CHUNK) {
#pragma unroll
            for (int u = 0; u < CHUNK; ++u) {
                const float2 e = ebuf[u];
                const int    m = mbuf[u];

                // masked arm: fwd keep s (exp(0)); bwd s*exp(e_new - e_old)
                const float Rx = __expf((e.x - ep.x) * dirf);
                const float Ry = __expf((e.y - ep.y) * dirf);
                const float sRx = s0 * Rx;
                const float sRy = s1 * Ry;
                const float wx = __expf(e.x);
                const float wy = __expf(e.y);
                const unsigned pbx = __float_as_uint(wx) + 0x3f800000u;
                const unsigned pby = __float_as_uint(wy) + 0x3f800000u;

                // gather own stream's 16-state (4x LDS.128 broadcast)
                u64 v[8];
                lds4(base + par, v);

                // prefetch (always in-bounds within the row)
                ebuf[u] = *epf;  epf += estep;
                mbuf[u] = *mpf;  mpf += mstep;

                // exponent fold: P = w * 2^-k from stream state[0]
                const unsigned ub  = (unsigned)v[0];
                const int kcur = (int)((ub >> 23) & 0xffu) - 127;
                const unsigned msk = ub & 0x7f800000u;
                const float Px = __uint_as_float(pbx - msk);
                const float Py = __uint_as_float(pby - msk);

                // two independent packed trees
                const float accx = dot16(v, Ca);
                const float accy = dot16(v, Cb);

                s0    = m ? (accx * Px) : sRx;
                s1    = m ? (accy * Py) : sRy;
                ksum += m * kcur;
                ep    = e;

                par ^= 256u;
                sts64(base + par + hb, s0, s1);
            }
        }

        // ---------------- join (all 32 lanes participate in every shfl) --------
        u64 vf[8];
        lds4(base + par, vf);
        const float y0 = dot16(vf, Ca);            // fwd lanes: (E^T alpha_2047)_j
        const float y1 = dot16(vf, Cb);

        const float d0 = __shfl_sync(0xffffffffu, s0,   lane ^ 16);
        const float d1 = __shfl_sync(0xffffffffu, s1,   lane ^ 16);
        const int   kB = __shfl_sync(0xffffffffu, ksum, lane ^ 16);

        const int mju = mrowb[(size_t)HALF * mstride];
        const float2 e2k = erow2[(size_t)HALF * 8];
        // m=1: logZ = sum_j y_j * delta_{2048,j}
        // m=0: beta_2047 = beta_2048 -> sum_j alpha_j * delta_j / w_{2048,j}
        const float t0 = mju ? (y0 * d0) : (s0 * d0 * __expf(-e2k.x));
        const float t1 = mju ? (y1 * d1) : (s1 * d1 * __expf(-e2k.y));

        float z = t0 + t1;
        z += __shfl_xor_sync(0xffffffffu, z, 4, 8);
        z += __shfl_xor_sync(0xffffffffu, z, 2, 8);
        z += __shfl_xor_sync(0xffffffffu, z, 1, 8);
        if (dir == 0 && h == 0)
            g_fwd[row] = logf(z) + (float)(ksum + kB) * 0.6931471805599453f;
    } else {
        // ---------------- gold path score (verbatim round 9) ----------------
        const int j   = lane & 15;
        const int row = blockIdx.x * 2 + (lane >> 4);
        const unsigned char* trow = tags_b + (size_t)row * S_LEN * tstride;
        const unsigned char* mrow = mask_b + (size_t)row * S_LEN * mstride;
        const float*         erow = emissions + (size_t)row * S_LEN * NT;

        float acc = 0.0f;
        int   cnt = 0;
        for (int t = j; t < S_LEN; t += 16) {
            const int tg = trow[(size_t)t * tstride];
            const int mm = mrow[(size_t)t * mstride];
            cnt += mm ? 1 : 0;
            if (t == 0) {
                acc += start_t[tg] + erow[tg];
            } else if (mm) {
                const int tpv = trow[(size_t)(t - 1) * tstride];
                acc += transitions[tpv * NT + tg] + erow[(size_t)t * NT + tg];
            }
        }
#pragma unroll
        for (int off = 8; off >= 1; off >>= 1) {
            acc += __shfl_xor_sync(0xffffffffu, acc, off, 16);
            cnt += __shfl_xor_sync(0xffffffffu, cnt, off, 16);
        }
        if (j == 0) {
            int last = cnt - 1;
            if (last < 0) last = 0;
            const int lt = trow[(size_t)last * tstride];
            g_gold[row] = acc + end_t[lt];
        }
    }

    // ---------------- last-block global reduction ----------------
    __syncthreads();
    if (threadIdx.x == 0) {
        __threadfence();
        const unsigned old = atomicAdd(&g_done, 1u);
        s_last = (old == NBLK - 1u) ? 1 : 0;
    }
    __syncthreads();
    if (s_last) {
        __threadfence();
        float a = 0.0f;
        for (int i = threadIdx.x; i < B_SZ; i += 64)
            a += g_fwd[i] - g_gold[i];
#pragma unroll
        for (int off = 16; off >= 1; off >>= 1)
            a += __shfl_xor_sync(0xffffffffu, a, off);
        __shared__ float wsum[2];
        if ((threadIdx.x & 31) == 0) wsum[threadIdx.x >> 5] = a;
        __syncthreads();
        if (threadIdx.x == 0) {
            out[0] = (wsum[0] + wsum[1]) * (1.0f / (float)B_SZ);
            g_done = 0;                      // reset for next graph replay
        }
    }
}

extern "C" void kernel_launch(void* const* d_in, const int* in_sizes, int n_in,
                              void* d_out, int out_size)
{
    (void)in_sizes; (void)n_in; (void)out_size;
    const float* emissions   = (const float*)d_in[0];
    const void*  tags        = d_in[1];
    const void*  mask        = d_in[2];
    const float* transitions = (const float*)d_in[3];
    const float* start_t     = (const float*)d_in[4];
    const float* end_t       = (const float*)d_in[5];

    crf_fused_kernel<<<NBLK, 64>>>(emissions, tags, mask, transitions,
                                   start_t, end_t, (float*)d_out);
}